// round 2
// baseline (speedup 1.0000x reference)
#include <cuda_runtime.h>
#include <math.h>

#define LSEQ 4096
#define DDIM 1024
#define SCALE 0.03125f   /* 1/sqrt(1024) */

// Scratch (device globals — allocation-free per harness rules)
__device__ float g_Q[LSEQ * DDIM];
__device__ float g_K[LSEQ * DDIM];
__device__ float g_V[LSEQ * DDIM];
__device__ float g_S[(size_t)LSEQ * LSEQ];

// ---------------------------------------------------------------------------
// Generic SGEMM: C[M,N] = A[M,K] @ B[K,N] + bias[N]
// 128x128 blocktile, BK=8, 256 threads, 8x8 per-thread microtile.
// Microtile operands fetched with LDS.128 (float4) to cut LDS issue count.
// ---------------------------------------------------------------------------
__global__ void __launch_bounds__(256) sgemm_bias_kernel(
    const float* __restrict__ A, const float* __restrict__ B,
    const float* __restrict__ bias, float* __restrict__ C,
    int M, int N, int Kd)
{
    __shared__ float As[8][128];
    __shared__ float Bs[8][128];
    const int tid = threadIdx.x;
    const int bn0 = blockIdx.x * 128;
    const int bm0 = blockIdx.y * 128;
    const int tx = tid & 15;
    const int ty = tid >> 4;
    const int aRow = tid >> 1;          // 0..127
    const int aCol = (tid & 1) * 4;     // 0 or 4
    const int bRow = tid >> 5;          // 0..7
    const int bCol = (tid & 31) * 4;    // 0..124

    float acc[8][8];
    #pragma unroll
    for (int i = 0; i < 8; i++)
        #pragma unroll
        for (int j = 0; j < 8; j++) acc[i][j] = 0.f;

    const float* Aptr = A + (size_t)(bm0 + aRow) * Kd + aCol;
    const float* Bptr = B + (size_t)bRow * N + bn0 + bCol;

    for (int k0 = 0; k0 < Kd; k0 += 8) {
        float4 av = *(const float4*)(Aptr + k0);
        float4 bv = *(const float4*)(Bptr + (size_t)k0 * N);
        As[aCol + 0][aRow] = av.x;
        As[aCol + 1][aRow] = av.y;
        As[aCol + 2][aRow] = av.z;
        As[aCol + 3][aRow] = av.w;
        *(float4*)&Bs[bRow][bCol] = bv;
        __syncthreads();
        #pragma unroll
        for (int k = 0; k < 8; k++) {
            float4 ra0 = *(const float4*)&As[k][ty * 8];
            float4 ra1 = *(const float4*)&As[k][ty * 8 + 4];
            float4 rb0 = *(const float4*)&Bs[k][tx * 8];
            float4 rb1 = *(const float4*)&Bs[k][tx * 8 + 4];
            float ra[8] = {ra0.x, ra0.y, ra0.z, ra0.w, ra1.x, ra1.y, ra1.z, ra1.w};
            float rb[8] = {rb0.x, rb0.y, rb0.z, rb0.w, rb1.x, rb1.y, rb1.z, rb1.w};
            #pragma unroll
            for (int i = 0; i < 8; i++)
                #pragma unroll
                for (int j = 0; j < 8; j++)
                    acc[i][j] += ra[i] * rb[j];
        }
        __syncthreads();
    }

    #pragma unroll
    for (int i = 0; i < 8; i++) {
        const int r = bm0 + ty * 8 + i;
        #pragma unroll
        for (int j = 0; j < 8; j += 4) {
            const int c = bn0 + tx * 8 + j;
            float4 o;
            o.x = acc[i][j + 0] + bias[c + 0];
            o.y = acc[i][j + 1] + bias[c + 1];
            o.z = acc[i][j + 2] + bias[c + 2];
            o.w = acc[i][j + 3] + bias[c + 3];
            *(float4*)&C[(size_t)r * N + c] = o;
        }
    }
}

// ---------------------------------------------------------------------------
// Scores: S[r,c] = Q[r,:] . K[c,:]   (raw, unscaled; only block-cols >= block-rows)
// ---------------------------------------------------------------------------
__global__ void __launch_bounds__(256) scores_kernel()
{
    const int bj = blockIdx.x;   // col block
    const int bi = blockIdx.y;   // row block
    if (bj < bi) return;         // fully masked: never read downstream

    __shared__ float As[8][128];
    __shared__ float Bs[8][128];
    const int tid = threadIdx.x;
    const int bn0 = bj * 128;
    const int bm0 = bi * 128;
    const int tx = tid & 15;
    const int ty = tid >> 4;
    const int aRow = tid >> 1;
    const int aCol = (tid & 1) * 4;

    float acc[8][8];
    #pragma unroll
    for (int i = 0; i < 8; i++)
        #pragma unroll
        for (int j = 0; j < 8; j++) acc[i][j] = 0.f;

    const float* Qptr = g_Q + (size_t)(bm0 + aRow) * DDIM + aCol;
    const float* Kptr = g_K + (size_t)(bn0 + aRow) * DDIM + aCol;

    for (int k0 = 0; k0 < DDIM; k0 += 8) {
        float4 qv = *(const float4*)(Qptr + k0);
        float4 kv = *(const float4*)(Kptr + k0);
        As[aCol + 0][aRow] = qv.x;
        As[aCol + 1][aRow] = qv.y;
        As[aCol + 2][aRow] = qv.z;
        As[aCol + 3][aRow] = qv.w;
        Bs[aCol + 0][aRow] = kv.x;
        Bs[aCol + 1][aRow] = kv.y;
        Bs[aCol + 2][aRow] = kv.z;
        Bs[aCol + 3][aRow] = kv.w;
        __syncthreads();
        #pragma unroll
        for (int k = 0; k < 8; k++) {
            float4 ra0 = *(const float4*)&As[k][ty * 8];
            float4 ra1 = *(const float4*)&As[k][ty * 8 + 4];
            float4 rb0 = *(const float4*)&Bs[k][tx * 8];
            float4 rb1 = *(const float4*)&Bs[k][tx * 8 + 4];
            float ra[8] = {ra0.x, ra0.y, ra0.z, ra0.w, ra1.x, ra1.y, ra1.z, ra1.w};
            float rb[8] = {rb0.x, rb0.y, rb0.z, rb0.w, rb1.x, rb1.y, rb1.z, rb1.w};
            #pragma unroll
            for (int i = 0; i < 8; i++)
                #pragma unroll
                for (int j = 0; j < 8; j++)
                    acc[i][j] += ra[i] * rb[j];
        }
        __syncthreads();
    }

    #pragma unroll
    for (int i = 0; i < 8; i++) {
        const int r = bm0 + ty * 8 + i;
        #pragma unroll
        for (int j = 0; j < 8; j += 4) {
            const int c = bn0 + tx * 8 + j;
            float4 o;
            o.x = acc[i][j + 0];
            o.y = acc[i][j + 1];
            o.z = acc[i][j + 2];
            o.w = acc[i][j + 3];
            *(float4*)&g_S[(size_t)r * LSEQ + c] = o;
        }
    }
}

// ---------------------------------------------------------------------------
// Softmax per row. Reads from the diagonal-aligned block start; applies the
// strictly-lower mask + 1/32 scale in-register; writes probabilities back
// (zeros fill the masked sub-diagonal slots so PV can read block-blindly).
// ---------------------------------------------------------------------------
__global__ void __launch_bounds__(256) softmax_kernel()
{
    __shared__ float sbuf[LSEQ];
    __shared__ float red[256];
    const int r = blockIdx.x;
    const int c0 = r & ~127;          // diagonal block start
    const int n = LSEQ - c0;
    float* row = g_S + (size_t)r * LSEQ + c0;
    const int tid = threadIdx.x;

    float lmax = -INFINITY;
    for (int j = tid; j < n; j += 256) {
        float v = row[j];
        v = (c0 + j < r) ? -INFINITY : v * SCALE;
        sbuf[j] = v;
        lmax = fmaxf(lmax, v);
    }
    red[tid] = lmax;
    __syncthreads();
    for (int s = 128; s > 0; s >>= 1) {
        if (tid < s) red[tid] = fmaxf(red[tid], red[tid + s]);
        __syncthreads();
    }
    const float m = red[0];
    __syncthreads();

    float lsum = 0.f;
    for (int j = tid; j < n; j += 256) {
        float e = __expf(sbuf[j] - m);
        sbuf[j] = e;
        lsum += e;
    }
    red[tid] = lsum;
    __syncthreads();
    for (int s = 128; s > 0; s >>= 1) {
        if (tid < s) red[tid] += red[tid + s];
        __syncthreads();
    }
    const float inv = 1.0f / red[0];
    __syncthreads();

    for (int j = tid; j < n; j += 256)
        row[j] = sbuf[j] * inv;
}

// ---------------------------------------------------------------------------
// O = P @ V with causal k-start (k begins at the row-block's diagonal).
// ---------------------------------------------------------------------------
__global__ void __launch_bounds__(256) pv_kernel(float* __restrict__ O)
{
    __shared__ float As[8][128];
    __shared__ float Bs[8][128];
    const int tid = threadIdx.x;
    const int bn0 = blockIdx.x * 128;
    const int bm0 = blockIdx.y * 128;
    const int tx = tid & 15;
    const int ty = tid >> 4;
    const int aRow = tid >> 1;
    const int aCol = (tid & 1) * 4;
    const int bRow = tid >> 5;
    const int bCol = (tid & 31) * 4;

    float acc[8][8];
    #pragma unroll
    for (int i = 0; i < 8; i++)
        #pragma unroll
        for (int j = 0; j < 8; j++) acc[i][j] = 0.f;

    const float* Aptr = g_S + (size_t)(bm0 + aRow) * LSEQ + aCol;
    const float* Bptr = g_V + (size_t)bRow * DDIM + bn0 + bCol;

    for (int k0 = bm0; k0 < LSEQ; k0 += 8) {   // causal start
        float4 av = *(const float4*)(Aptr + k0);
        float4 bv = *(const float4*)(Bptr + (size_t)k0 * DDIM);
        As[aCol + 0][aRow] = av.x;
        As[aCol + 1][aRow] = av.y;
        As[aCol + 2][aRow] = av.z;
        As[aCol + 3][aRow] = av.w;
        *(float4*)&Bs[bRow][bCol] = bv;
        __syncthreads();
        #pragma unroll
        for (int k = 0; k < 8; k++) {
            float4 ra0 = *(const float4*)&As[k][ty * 8];
            float4 ra1 = *(const float4*)&As[k][ty * 8 + 4];
            float4 rb0 = *(const float4*)&Bs[k][tx * 8];
            float4 rb1 = *(const float4*)&Bs[k][tx * 8 + 4];
            float ra[8] = {ra0.x, ra0.y, ra0.z, ra0.w, ra1.x, ra1.y, ra1.z, ra1.w};
            float rb[8] = {rb0.x, rb0.y, rb0.z, rb0.w, rb1.x, rb1.y, rb1.z, rb1.w};
            #pragma unroll
            for (int i = 0; i < 8; i++)
                #pragma unroll
                for (int j = 0; j < 8; j++)
                    acc[i][j] += ra[i] * rb[j];
        }
        __syncthreads();
    }

    #pragma unroll
    for (int i = 0; i < 8; i++) {
        const int r = bm0 + ty * 8 + i;
        #pragma unroll
        for (int j = 0; j < 8; j += 4) {
            const int c = bn0 + tx * 8 + j;
            float4 o;
            o.x = acc[i][j + 0];
            o.y = acc[i][j + 1];
            o.z = acc[i][j + 2];
            o.w = acc[i][j + 3];
            *(float4*)&O[(size_t)r * DDIM + c] = o;
        }
    }
}

// ---------------------------------------------------------------------------
extern "C" void kernel_launch(void* const* d_in, const int* in_sizes, int n_in,
                              void* d_out, int out_size)
{
    const float* x  = (const float*)d_in[0];
    const float* z  = (const float*)d_in[1];
    const float* Wq = (const float*)d_in[2];
    const float* bq = (const float*)d_in[3];
    const float* Wk = (const float*)d_in[4];
    const float* bk = (const float*)d_in[5];
    const float* Wv = (const float*)d_in[6];
    const float* bv = (const float*)d_in[7];
    float* out = (float*)d_out;

    float *Qd, *Kd, *Vd;
    cudaGetSymbolAddress((void**)&Qd, g_Q);
    cudaGetSymbolAddress((void**)&Kd, g_K);
    cudaGetSymbolAddress((void**)&Vd, g_V);

    dim3 blk(256);
    dim3 gProj(DDIM / 128, LSEQ / 128);     // (8, 32)
    sgemm_bias_kernel<<<gProj, blk>>>(x, Wq, bq, Qd, LSEQ, DDIM, DDIM);
    sgemm_bias_kernel<<<gProj, blk>>>(z, Wk, bk, Kd, LSEQ, DDIM, DDIM);
    sgemm_bias_kernel<<<gProj, blk>>>(z, Wv, bv, Vd, LSEQ, DDIM, DDIM);

    dim3 gScores(LSEQ / 128, LSEQ / 128);   // (32, 32), lower blocks early-exit
    scores_kernel<<<gScores, blk>>>();

    softmax_kernel<<<LSEQ, blk>>>();

    dim3 gPV(DDIM / 128, LSEQ / 128);       // (8, 32)
    pv_kernel<<<gPV, blk>>>(out);
}

// round 15
// speedup vs baseline: 3.5419x; 3.5419x over previous
#include <cuda_runtime.h>
#include <cuda_bf16.h>
#include <cstdint>
#include <math.h>

#define LSEQ 4096
#define DDIM 1024
#define SCALE 0.03125f   /* 1/sqrt(1024) */
#define TILEB 16384      /* one 128x64 bf16 tile, SW128-swizzled */
#define SMEM_GEMM_BYTES (8 * TILEB)   /* 131072: 4 tiles x 2 stages */

// ---------------------------------------------------------------------------
// Scratch (device globals — allocation-free per harness rules)
// ---------------------------------------------------------------------------
__device__ __nv_bfloat16 g_Xh[LSEQ * DDIM], g_Xl[LSEQ * DDIM];
__device__ __nv_bfloat16 g_Zh[LSEQ * DDIM], g_Zl[LSEQ * DDIM];
__device__ __nv_bfloat16 g_Wqh[DDIM * DDIM], g_Wql[DDIM * DDIM];
__device__ __nv_bfloat16 g_Wkh[DDIM * DDIM], g_Wkl[DDIM * DDIM];
__device__ __nv_bfloat16 g_Wvh[DDIM * DDIM], g_Wvl[DDIM * DDIM];
__device__ __nv_bfloat16 g_Qh[LSEQ * DDIM], g_Ql[LSEQ * DDIM];
__device__ __nv_bfloat16 g_Kh[LSEQ * DDIM], g_Kl[LSEQ * DDIM];
__device__ __nv_bfloat16 g_Vth[DDIM * LSEQ], g_Vtl[DDIM * LSEQ];   // V transposed [dim, seq]
__device__ __nv_bfloat16 g_Ph[(size_t)LSEQ * LSEQ], g_Pl[(size_t)LSEQ * LSEQ];
__device__ float g_S[(size_t)LSEQ * LSEQ];

// ---------------------------------------------------------------------------
// Helpers (family-wide PTX only: sm_80+ features, legal under compute_103)
// ---------------------------------------------------------------------------
__device__ __forceinline__ uint32_t smem_u32(const void* p) {
    uint32_t a;
    asm("{ .reg .u64 t; cvta.to.shared.u64 t, %1; cvt.u32.u64 %0, t; }" : "=r"(a) : "l"(p));
    return a;
}

#define SMEM_SW128(b) ((b) ^ (((b) >> 3) & 0x70))

__device__ __forceinline__ void cp_async16(uint32_t dst, const void* src) {
    asm volatile("cp.async.cg.shared.global [%0], [%1], 16;" :: "r"(dst), "l"(src));
}
#define CP_ASYNC_COMMIT() asm volatile("cp.async.commit_group;" ::: "memory")
#define CP_ASYNC_WAIT_ALL() asm volatile("cp.async.wait_group 0;" ::: "memory")

__device__ __forceinline__ void ldm_x4(uint32_t& r0, uint32_t& r1, uint32_t& r2, uint32_t& r3,
                                       uint32_t addr) {
    asm volatile("ldmatrix.sync.aligned.m8n8.x4.shared.b16 {%0,%1,%2,%3}, [%4];"
        : "=r"(r0), "=r"(r1), "=r"(r2), "=r"(r3) : "r"(addr));
}

__device__ __forceinline__ void mma16816(float* c, const uint32_t* a, const uint32_t* b) {
    asm volatile("mma.sync.aligned.m16n8k16.row.col.f32.bf16.bf16.f32 "
        "{%0,%1,%2,%3}, {%4,%5,%6,%7}, {%8,%9}, {%0,%1,%2,%3};"
        : "+f"(c[0]), "+f"(c[1]), "+f"(c[2]), "+f"(c[3])
        : "r"(a[0]), "r"(a[1]), "r"(a[2]), "r"(a[3]), "r"(b[0]), "r"(b[1]));
}

__device__ __forceinline__ void split1(float v, __nv_bfloat16& h, __nv_bfloat16& l) {
    h = __float2bfloat16(v);
    l = __float2bfloat16(v - __bfloat162float(h));
}

__device__ __forceinline__ uint32_t pack2(__nv_bfloat16 a, __nv_bfloat16 b) {
    return (uint32_t)__bfloat16_as_ushort(a) | ((uint32_t)__bfloat16_as_ushort(b) << 16);
}

// ---------------------------------------------------------------------------
// Async-load one 128x64 bf16 tile into SW128-swizzled SMEM (1024 x 16B).
// ---------------------------------------------------------------------------
__device__ __forceinline__ void load_tile_async(uint32_t dst, const __nv_bfloat16* __restrict__ src,
                                                int stride, int tid) {
    #pragma unroll
    for (int it = 0; it < 4; it++) {
        int idx = tid + it * 256;
        int row = idx >> 3;
        int c = idx & 7;
        const char* g = (const char*)(src + (size_t)row * stride) + c * 16;
        uint32_t boff = (uint32_t)(row * 128 + c * 16);
        cp_async16(dst + SMEM_SW128(boff), g);
    }
}

__device__ __forceinline__ void load_chunk_async(uint32_t st,
    const __nv_bfloat16* Ah, const __nv_bfloat16* Al, int sA,
    const __nv_bfloat16* Bh, const __nv_bfloat16* Bl, int sB, int tid) {
    load_tile_async(st + 0 * TILEB, Ah, sA, tid);
    load_tile_async(st + 1 * TILEB, Al, sA, tid);
    load_tile_async(st + 2 * TILEB, Bh, sB, tid);
    load_tile_async(st + 3 * TILEB, Bl, sB, tid);
}

// ---------------------------------------------------------------------------
// Compute one BK=64 chunk from stage st: acc += Ah*Bh^T + Ah*Bl^T + Al*Bh^T.
// Warp w: wm = w&3 (32 rows), wn = w>>2 (64 cols). acc[2][8][4] per thread.
// ---------------------------------------------------------------------------
__device__ __forceinline__ void compute_chunk(uint32_t st, float acc[2][8][4], int tid) {
    const int lane = tid & 31;
    const int warp = tid >> 5;
    const int wm = warp & 3;
    const int wn = warp >> 2;
    const int g = lane >> 3;
    const int r = lane & 7;
    const uint32_t Ah = st, Al = st + TILEB, Bh = st + 2 * TILEB, Bl = st + 3 * TILEB;

    #pragma unroll
    for (int ks = 0; ks < 4; ks++) {
        const int kb = ks * 32;   // byte offset of k-step (16 bf16 = 32 B)
        uint32_t ahf[2][4], alf[2][4];
        #pragma unroll
        for (int mt = 0; mt < 2; mt++) {
            int row = wm * 32 + mt * 16 + (g & 1) * 8 + r;
            uint32_t boff = SMEM_SW128((uint32_t)(row * 128 + kb + (g >> 1) * 16));
            ldm_x4(ahf[mt][0], ahf[mt][1], ahf[mt][2], ahf[mt][3], Ah + boff);
            ldm_x4(alf[mt][0], alf[mt][1], alf[mt][2], alf[mt][3], Al + boff);
        }
        uint32_t bhf[8][2], blf[8][2];
        #pragma unroll
        for (int ng = 0; ng < 4; ng++) {
            int rowB = wn * 64 + ng * 16 + (g >> 1) * 8 + r;
            uint32_t boff = SMEM_SW128((uint32_t)(rowB * 128 + kb + (g & 1) * 16));
            uint32_t t0, t1, t2, t3;
            ldm_x4(t0, t1, t2, t3, Bh + boff);
            bhf[2 * ng][0] = t0; bhf[2 * ng][1] = t1;
            bhf[2 * ng + 1][0] = t2; bhf[2 * ng + 1][1] = t3;
            ldm_x4(t0, t1, t2, t3, Bl + boff);
            blf[2 * ng][0] = t0; blf[2 * ng][1] = t1;
            blf[2 * ng + 1][0] = t2; blf[2 * ng + 1][1] = t3;
        }
        #pragma unroll
        for (int mt = 0; mt < 2; mt++)
            #pragma unroll
            for (int nt = 0; nt < 8; nt++) {
                mma16816(acc[mt][nt], ahf[mt], bhf[nt]);
                mma16816(acc[mt][nt], ahf[mt], blf[nt]);
                mma16816(acc[mt][nt], alf[mt], bhf[nt]);
            }
    }
}

// ---------------------------------------------------------------------------
// Shared mainloop over k in [kbeg, kend), BK=64, 2-stage cp.async pipeline.
// ---------------------------------------------------------------------------
__device__ __forceinline__ void run_gemm3(uint32_t smem_base, float acc[2][8][4],
    const __nv_bfloat16* __restrict__ Ah, const __nv_bfloat16* __restrict__ Al, int sA,
    const __nv_bfloat16* __restrict__ Bh, const __nv_bfloat16* __restrict__ Bl, int sB,
    int kbeg, int kend, int tid)
{
    #pragma unroll
    for (int mt = 0; mt < 2; mt++)
        #pragma unroll
        for (int nt = 0; nt < 8; nt++)
            #pragma unroll
            for (int i = 0; i < 4; i++) acc[mt][nt][i] = 0.f;

    const int nch = (kend - kbeg) >> 6;
    load_chunk_async(smem_base, Ah + kbeg, Al + kbeg, sA, Bh + kbeg, Bl + kbeg, sB, tid);
    CP_ASYNC_COMMIT();
    CP_ASYNC_WAIT_ALL();
    __syncthreads();
    for (int c = 0; c < nch; c++) {
        const int s = c & 1;
        if (c + 1 < nch) {
            const int k0 = kbeg + (c + 1) * 64;
            load_chunk_async(smem_base + (uint32_t)(s ^ 1) * 4 * TILEB,
                             Ah + k0, Al + k0, sA, Bh + k0, Bl + k0, sB, tid);
            CP_ASYNC_COMMIT();
        }
        compute_chunk(smem_base + (uint32_t)s * 4 * TILEB, acc, tid);
        CP_ASYNC_WAIT_ALL();
        __syncthreads();
    }
}

// ---------------------------------------------------------------------------
// Projection: C = A @ Wt^T + bias; epilogue splits to bf16 hi/lo.
// transposeOut=0: C [4096,1024] -> Ch/Cl. transposeOut=1: -> Vt [1024,4096].
// ---------------------------------------------------------------------------
__global__ void __launch_bounds__(256, 1) proj_kernel(
    const __nv_bfloat16* __restrict__ Ah, const __nv_bfloat16* __restrict__ Al,
    const __nv_bfloat16* __restrict__ Bh, const __nv_bfloat16* __restrict__ Bl,
    const float* __restrict__ bias,
    __nv_bfloat16* __restrict__ Ch, __nv_bfloat16* __restrict__ Cl,
    int transposeOut)
{
    extern __shared__ char smem[];
    const uint32_t smem_base = smem_u32(smem);
    const int tid = threadIdx.x;
    const int bn0 = blockIdx.x * 128;
    const int bm0 = blockIdx.y * 128;

    float acc[2][8][4];
    run_gemm3(smem_base, acc,
              Ah + (size_t)bm0 * DDIM, Al + (size_t)bm0 * DDIM, DDIM,
              Bh + (size_t)bn0 * DDIM, Bl + (size_t)bn0 * DDIM, DDIM,
              0, DDIM, tid);

    const int lane = tid & 31, warp = tid >> 5;
    const int wm = warp & 3, wn = warp >> 2;
    const int qr = lane >> 2, qc = (lane & 3) * 2;
    #pragma unroll
    for (int mt = 0; mt < 2; mt++)
        #pragma unroll
        for (int half = 0; half < 2; half++) {
            const int m = bm0 + wm * 32 + mt * 16 + half * 8 + qr;
            #pragma unroll
            for (int nt = 0; nt < 8; nt++) {
                const int c = bn0 + wn * 64 + nt * 8 + qc;
                float v0 = acc[mt][nt][half * 2 + 0] + bias[c];
                float v1 = acc[mt][nt][half * 2 + 1] + bias[c + 1];
                __nv_bfloat16 h0, l0, h1, l1;
                split1(v0, h0, l0); split1(v1, h1, l1);
                if (!transposeOut) {
                    *(uint32_t*)&Ch[(size_t)m * DDIM + c] = pack2(h0, h1);
                    *(uint32_t*)&Cl[(size_t)m * DDIM + c] = pack2(l0, l1);
                } else {
                    Ch[(size_t)c * LSEQ + m] = h0;       Cl[(size_t)c * LSEQ + m] = l0;
                    Ch[(size_t)(c + 1) * LSEQ + m] = h1; Cl[(size_t)(c + 1) * LSEQ + m] = l1;
                }
            }
        }
}

// ---------------------------------------------------------------------------
// Scores: S = Q @ K^T (raw fp32), upper-triangular blocks only.
// ---------------------------------------------------------------------------
__global__ void __launch_bounds__(256, 1) scores_kernel()
{
    const int bj = blockIdx.x, bi = blockIdx.y;
    if (bj < bi) return;
    extern __shared__ char smem[];
    const uint32_t smem_base = smem_u32(smem);
    const int tid = threadIdx.x;
    const int bn0 = bj * 128, bm0 = bi * 128;

    float acc[2][8][4];
    run_gemm3(smem_base, acc,
              g_Qh + (size_t)bm0 * DDIM, g_Ql + (size_t)bm0 * DDIM, DDIM,
              g_Kh + (size_t)bn0 * DDIM, g_Kl + (size_t)bn0 * DDIM, DDIM,
              0, DDIM, tid);

    const int lane = tid & 31, warp = tid >> 5;
    const int wm = warp & 3, wn = warp >> 2;
    const int qr = lane >> 2, qc = (lane & 3) * 2;
    #pragma unroll
    for (int mt = 0; mt < 2; mt++)
        #pragma unroll
        for (int half = 0; half < 2; half++) {
            const int m = bm0 + wm * 32 + mt * 16 + half * 8 + qr;
            #pragma unroll
            for (int nt = 0; nt < 8; nt++) {
                const int c = bn0 + wn * 64 + nt * 8 + qc;
                float2 o = make_float2(acc[mt][nt][half * 2 + 0], acc[mt][nt][half * 2 + 1]);
                *(float2*)&g_S[(size_t)m * LSEQ + c] = o;
            }
        }
}

// ---------------------------------------------------------------------------
// PV: O = P @ Vt^T, causal k-start at the row block's diagonal.
// ---------------------------------------------------------------------------
__global__ void __launch_bounds__(256, 1) pv_kernel(float* __restrict__ O)
{
    extern __shared__ char smem[];
    const uint32_t smem_base = smem_u32(smem);
    const int tid = threadIdx.x;
    const int bn0 = blockIdx.x * 128;
    const int bm0 = blockIdx.y * 128;

    float acc[2][8][4];
    run_gemm3(smem_base, acc,
              g_Ph + (size_t)bm0 * LSEQ, g_Pl + (size_t)bm0 * LSEQ, LSEQ,
              g_Vth + (size_t)bn0 * LSEQ, g_Vtl + (size_t)bn0 * LSEQ, LSEQ,
              bm0, LSEQ, tid);

    const int lane = tid & 31, warp = tid >> 5;
    const int wm = warp & 3, wn = warp >> 2;
    const int qr = lane >> 2, qc = (lane & 3) * 2;
    #pragma unroll
    for (int mt = 0; mt < 2; mt++)
        #pragma unroll
        for (int half = 0; half < 2; half++) {
            const int m = bm0 + wm * 32 + mt * 16 + half * 8 + qr;
            #pragma unroll
            for (int nt = 0; nt < 8; nt++) {
                const int c = bn0 + wn * 64 + nt * 8 + qc;
                float2 o = make_float2(acc[mt][nt][half * 2 + 0], acc[mt][nt][half * 2 + 1]);
                *(float2*)&O[(size_t)m * DDIM + c] = o;
            }
        }
}

// ---------------------------------------------------------------------------
// Softmax per row: reads fp32 S, writes split bf16 P (zeros in masked slots).
// ---------------------------------------------------------------------------
__global__ void __launch_bounds__(256) softmax_kernel()
{
    __shared__ float sbuf[LSEQ];
    __shared__ float red[256];
    const int r = blockIdx.x;
    const int c0 = r & ~127;          // diagonal block start
    const int n = LSEQ - c0;
    const float* row = g_S + (size_t)r * LSEQ + c0;
    const size_t pbase = (size_t)r * LSEQ + c0;
    const int tid = threadIdx.x;

    float lmax = -INFINITY;
    for (int j = tid; j < n; j += 256) {
        float v = row[j];
        v = (c0 + j < r) ? -INFINITY : v * SCALE;
        sbuf[j] = v;
        lmax = fmaxf(lmax, v);
    }
    red[tid] = lmax;
    __syncthreads();
    for (int s = 128; s > 0; s >>= 1) {
        if (tid < s) red[tid] = fmaxf(red[tid], red[tid + s]);
        __syncthreads();
    }
    const float m = red[0];
    __syncthreads();

    float lsum = 0.f;
    for (int j = tid; j < n; j += 256) {
        float e = __expf(sbuf[j] - m);
        sbuf[j] = e;
        lsum += e;
    }
    red[tid] = lsum;
    __syncthreads();
    for (int s = 128; s > 0; s >>= 1) {
        if (tid < s) red[tid] += red[tid + s];
        __syncthreads();
    }
    const float inv = 1.0f / red[0];
    __syncthreads();

    for (int j = tid; j < n; j += 256) {
        float p = sbuf[j] * inv;
        __nv_bfloat16 h, l;
        split1(p, h, l);
        g_Ph[pbase + j] = h;
        g_Pl[pbase + j] = l;
    }
}

// ---------------------------------------------------------------------------
// Elementwise fp32 -> bf16 hi/lo split (vectorized).
// ---------------------------------------------------------------------------
__global__ void __launch_bounds__(256) split_rows_kernel(
    const float* __restrict__ src, __nv_bfloat16* __restrict__ h,
    __nv_bfloat16* __restrict__ l, int n4)
{
    int i = blockIdx.x * blockDim.x + threadIdx.x;
    const int stride = gridDim.x * blockDim.x;
    for (; i < n4; i += stride) {
        float4 v = ((const float4*)src)[i];
        __nv_bfloat16 h0, l0, h1, l1, h2, l2, h3, l3;
        split1(v.x, h0, l0); split1(v.y, h1, l1);
        split1(v.z, h2, l2); split1(v.w, h3, l3);
        uint2 hv = make_uint2(pack2(h0, h1), pack2(h2, h3));
        uint2 lv = make_uint2(pack2(l0, l1), pack2(l2, l3));
        ((uint2*)h)[i] = hv;
        ((uint2*)l)[i] = lv;
    }
}

// ---------------------------------------------------------------------------
// W [K,N] -> Wt [N,K] transpose + bf16 split. 32x32 tiles, block (32,8).
// ---------------------------------------------------------------------------
__global__ void __launch_bounds__(256) split_transpose_kernel(
    const float* __restrict__ W, __nv_bfloat16* __restrict__ Th,
    __nv_bfloat16* __restrict__ Tl)
{
    __shared__ float t[32][33];
    const int n0 = blockIdx.x * 32, k0 = blockIdx.y * 32;
    const int tx = threadIdx.x, ty = threadIdx.y;
    for (int rr = ty; rr < 32; rr += 8)
        t[rr][tx] = W[(size_t)(k0 + rr) * DDIM + n0 + tx];
    __syncthreads();
    for (int rr = ty; rr < 32; rr += 8) {
        float v = t[tx][rr];   // = W[k0+tx][n0+rr]
        __nv_bfloat16 h, l;
        split1(v, h, l);
        size_t o = (size_t)(n0 + rr) * DDIM + k0 + tx;
        Th[o] = h;
        Tl[o] = l;
    }
}

// ---------------------------------------------------------------------------
extern "C" void kernel_launch(void* const* d_in, const int* in_sizes, int n_in,
                              void* d_out, int out_size)
{
    const float* x  = (const float*)d_in[0];
    const float* z  = (const float*)d_in[1];
    const float* Wq = (const float*)d_in[2];
    const float* bq = (const float*)d_in[3];
    const float* Wk = (const float*)d_in[4];
    const float* bk = (const float*)d_in[5];
    const float* Wv = (const float*)d_in[6];
    const float* bv = (const float*)d_in[7];
    float* out = (float*)d_out;

    // Idempotent, not stream-ordered: safe every invocation (no static guards).
    cudaFuncSetAttribute(proj_kernel,   cudaFuncAttributeMaxDynamicSharedMemorySize, SMEM_GEMM_BYTES);
    cudaFuncSetAttribute(scores_kernel, cudaFuncAttributeMaxDynamicSharedMemorySize, SMEM_GEMM_BYTES);
    cudaFuncSetAttribute(pv_kernel,     cudaFuncAttributeMaxDynamicSharedMemorySize, SMEM_GEMM_BYTES);

    __nv_bfloat16 *Xh, *Xl, *Zh, *Zl, *Wqh, *Wql, *Wkh, *Wkl, *Wvh, *Wvl;
    __nv_bfloat16 *Qh, *Ql, *Kh, *Kl, *Vth, *Vtl;
    cudaGetSymbolAddress((void**)&Xh, g_Xh);   cudaGetSymbolAddress((void**)&Xl, g_Xl);
    cudaGetSymbolAddress((void**)&Zh, g_Zh);   cudaGetSymbolAddress((void**)&Zl, g_Zl);
    cudaGetSymbolAddress((void**)&Wqh, g_Wqh); cudaGetSymbolAddress((void**)&Wql, g_Wql);
    cudaGetSymbolAddress((void**)&Wkh, g_Wkh); cudaGetSymbolAddress((void**)&Wkl, g_Wkl);
    cudaGetSymbolAddress((void**)&Wvh, g_Wvh); cudaGetSymbolAddress((void**)&Wvl, g_Wvl);
    cudaGetSymbolAddress((void**)&Qh, g_Qh);   cudaGetSymbolAddress((void**)&Ql, g_Ql);
    cudaGetSymbolAddress((void**)&Kh, g_Kh);   cudaGetSymbolAddress((void**)&Kl, g_Kl);
    cudaGetSymbolAddress((void**)&Vth, g_Vth); cudaGetSymbolAddress((void**)&Vtl, g_Vtl);

    // Split inputs to bf16 hi/lo
    const int n4 = LSEQ * DDIM / 4;
    split_rows_kernel<<<2048, 256>>>(x, Xh, Xl, n4);
    split_rows_kernel<<<2048, 256>>>(z, Zh, Zl, n4);
    dim3 tb(32, 8);
    dim3 tg(DDIM / 32, DDIM / 32);
    split_transpose_kernel<<<tg, tb>>>(Wq, Wqh, Wql);
    split_transpose_kernel<<<tg, tb>>>(Wk, Wkh, Wkl);
    split_transpose_kernel<<<tg, tb>>>(Wv, Wvh, Wvl);

    // Projections
    dim3 gProj(DDIM / 128, LSEQ / 128);   // (8, 32)
    proj_kernel<<<gProj, 256, SMEM_GEMM_BYTES>>>(Xh, Xl, Wqh, Wql, bq, Qh, Ql, 0);
    proj_kernel<<<gProj, 256, SMEM_GEMM_BYTES>>>(Zh, Zl, Wkh, Wkl, bk, Kh, Kl, 0);
    proj_kernel<<<gProj, 256, SMEM_GEMM_BYTES>>>(Zh, Zl, Wvh, Wvl, bv, Vth, Vtl, 1);

    // Scores (upper blocks), softmax, PV
    dim3 gScores(LSEQ / 128, LSEQ / 128); // (32, 32); lower blocks early-exit
    scores_kernel<<<gScores, 256, SMEM_GEMM_BYTES>>>();
    softmax_kernel<<<LSEQ, 256>>>();
    dim3 gPV(DDIM / 128, LSEQ / 128);     // (8, 32)
    pv_kernel<<<gPV, 256, SMEM_GEMM_BYTES>>>(out);
}